// round 14
// baseline (speedup 1.0000x reference)
#include <cuda_runtime.h>
#include <cuda_bf16.h>
#include <cuda_fp16.h>
#include <cstdint>

#define B_   16
#define C_   128
#define HW_  1024
#define NH_  4
#define COND_ 32

// Scratch (device globals; no allocations allowed)
__device__ __nv_bfloat16  g_h16 [B_*C_*HW_];
__device__ __nv_bfloat16  g_q16 [B_*NH_*HW_*C_];
__device__ __nv_bfloat16  g_k16 [B_*NH_*HW_*C_];
__device__ __half         g_v16h[B_*NH_*HW_*C_];
__device__ __nv_bfloat16  g_hh16[B_*6*C_*HW_];
__device__ __nv_bfloat16  g_w0b[160*512];
__device__ __nv_bfloat16  g_w1b[160*512];
__device__ __nv_bfloat16  g_w2b[160*512];
__device__ __nv_bfloat16  g_w3b[768*128];
__device__ __nv_bfloat16  g_qcb[(B_/2)*COND_*HW_];
__device__ __nv_bfloat16  g_kab[(B_/2)*COND_*HW_];
__device__ __nv_bfloat16  g_kbb[(B_/2)*COND_*HW_];

// ---------------------------------------------------------------------------
__device__ __forceinline__ uint32_t smem_u32(const void* p) {
    uint32_t a;
    asm("{ .reg .u64 t; cvta.to.shared.u64 t, %1; cvt.u32.u64 %0, t; }"
        : "=r"(a) : "l"(p));
    return a;
}
__device__ __forceinline__ uint32_t pack_bf16(float lo, float hi) {
    uint32_t r;
    asm("cvt.rn.bf16x2.f32 %0, %1, %2;" : "=r"(r) : "f"(hi), "f"(lo));
    return r;
}
__device__ __forceinline__ uint32_t pack_f16(float lo, float hi) {
    __half2 h = __floats2half2_rn(lo, hi);
    return *(uint32_t*)&h;
}
__device__ __forceinline__ float fast_ex2(float x) {
    float y;
    asm("ex2.approx.f32 %0, %1;" : "=f"(y) : "f"(x));
    return y;
}
__device__ __forceinline__ void mma_bf16(float c[4], const uint32_t a[4],
                                         uint32_t b0, uint32_t b1) {
    asm volatile("mma.sync.aligned.m16n8k16.row.col.f32.bf16.bf16.f32 "
        "{%0,%1,%2,%3}, {%4,%5,%6,%7}, {%8,%9}, {%0,%1,%2,%3};"
        : "+f"(c[0]), "+f"(c[1]), "+f"(c[2]), "+f"(c[3])
        : "r"(a[0]), "r"(a[1]), "r"(a[2]), "r"(a[3]), "r"(b0), "r"(b1));
}
__device__ __forceinline__ void mma_f16acc(uint32_t c[2], const uint32_t a[4],
                                           uint32_t b0, uint32_t b1) {
    asm volatile("mma.sync.aligned.m16n8k16.row.col.f16.f16.f16.f16 "
        "{%0,%1}, {%2,%3,%4,%5}, {%6,%7}, {%0,%1};"
        : "+r"(c[0]), "+r"(c[1])
        : "r"(a[0]), "r"(a[1]), "r"(a[2]), "r"(a[3]), "r"(b0), "r"(b1));
}
__device__ __forceinline__ void ldsm_x4(uint32_t r[4], uint32_t addr) {
    asm volatile("ldmatrix.sync.aligned.m8n8.x4.shared.b16 {%0,%1,%2,%3}, [%4];"
        : "=r"(r[0]), "=r"(r[1]), "=r"(r[2]), "=r"(r[3]) : "r"(addr));
}
__device__ __forceinline__ void ldsm_x4t(uint32_t r[4], uint32_t addr) {
    asm volatile("ldmatrix.sync.aligned.m8n8.x4.trans.shared.b16 {%0,%1,%2,%3}, [%4];"
        : "=r"(r[0]), "=r"(r[1]), "=r"(r[2]), "=r"(r[3]) : "r"(addr));
}
__device__ __forceinline__ void cp_async16(uint32_t dst, const void* src) {
    asm volatile("cp.async.cg.shared.global [%0], [%1], 16;"
                 :: "r"(dst), "l"(src) : "memory");
}
#define CP_COMMIT() asm volatile("cp.async.commit_group;" ::: "memory")
#define CP_WAIT1()  asm volatile("cp.async.wait_group 1;" ::: "memory")
#define CP_WAIT0()  asm volatile("cp.async.wait_group 0;" ::: "memory")

// ---------------------------------------------------------------------------
// Fused GroupNorm (blocks 0..511) + fp32->bf16 convert (blocks 512+)
// ---------------------------------------------------------------------------
__global__ void __launch_bounds__(256) gncvt_kernel(
    const float* __restrict__ x, const float* __restrict__ scale,
    const float* __restrict__ bias, __nv_bfloat16* __restrict__ h,
    const float* __restrict__ W0, const float* __restrict__ W1,
    const float* __restrict__ W2, const float* __restrict__ W3,
    const float* __restrict__ qc, const float* __restrict__ ka,
    const float* __restrict__ kb)
{
    int blk = blockIdx.x;
    if (blk >= 512) {
        int j = blk - 512;
        const float* src; __nv_bfloat16* dst; int base;
        if      (j < 80)   { src = W0; dst = g_w0b; base = j; }
        else if (j < 160)  { src = W1; dst = g_w1b; base = j - 80; }
        else if (j < 240)  { src = W2; dst = g_w2b; base = j - 160; }
        else if (j < 336)  { src = W3; dst = g_w3b; base = j - 240; }
        else if (j < 592)  { src = qc; dst = g_qcb; base = j - 336; }
        else if (j < 848)  { src = ka; dst = g_kab; base = j - 592; }
        else               { src = kb; dst = g_kbb; base = j - 848; }
        int i = base*1024 + threadIdx.x*4;
        float4 v = *(const float4*)&src[i];
        *(uint2*)&dst[i] = make_uint2(pack_bf16(v.x, v.y), pack_bf16(v.z, v.w));
        return;
    }

    int b = blk >> 5, grp = blk & 31;
    const float* xp = x + (size_t)(b*C_ + grp*4)*HW_;
    __nv_bfloat16* hp = h + (size_t)(b*C_ + grp*4)*HW_;

    float v[16];
    float s = 0.f, ss = 0.f;
    #pragma unroll
    for (int it = 0; it < 4; it++) {
        int i = (it*256 + threadIdx.x)*4;
        float4 q = *(const float4*)&xp[i];
        v[it*4+0] = q.x; v[it*4+1] = q.y; v[it*4+2] = q.z; v[it*4+3] = q.w;
        s  += (q.x + q.y) + (q.z + q.w);
        ss += (q.x*q.x + q.y*q.y) + (q.z*q.z + q.w*q.w);
    }
    #pragma unroll
    for (int o = 16; o; o >>= 1) {
        s  += __shfl_xor_sync(~0u, s,  o);
        ss += __shfl_xor_sync(~0u, ss, o);
    }
    __shared__ float sh_s[8], sh_ss[8];
    int w = threadIdx.x >> 5;
    if ((threadIdx.x & 31) == 0) { sh_s[w] = s; sh_ss[w] = ss; }
    __syncthreads();
    if (threadIdx.x < 32) {
        s  = (threadIdx.x < 8) ? sh_s [threadIdx.x] : 0.f;
        ss = (threadIdx.x < 8) ? sh_ss[threadIdx.x] : 0.f;
        #pragma unroll
        for (int o = 4; o; o >>= 1) {
            s  += __shfl_xor_sync(~0u, s,  o);
            ss += __shfl_xor_sync(~0u, ss, o);
        }
        if (threadIdx.x == 0) { sh_s[0] = s; sh_ss[0] = ss; }
    }
    __syncthreads();
    float mean = sh_s[0] * (1.f/4096.f);
    float var  = sh_ss[0] * (1.f/4096.f) - mean*mean;
    float inv  = rsqrtf(var + 1e-6f);
    #pragma unroll
    for (int it = 0; it < 4; it++) {
        int i = (it*256 + threadIdx.x)*4;
        int c = grp*4 + (i >> 10);
        float sc = scale[c]*inv, bi = bias[c] - mean*scale[c]*inv;
        uint2 pk = make_uint2(pack_bf16(v[it*4+0]*sc + bi, v[it*4+1]*sc + bi),
                              pack_bf16(v[it*4+2]*sc + bi, v[it*4+3]*sc + bi));
        *(uint2*)&hp[i] = pk;
    }
}

// ---------------------------------------------------------------------------
// QKV projection. q,k -> bf16; v -> fp16.
// ---------------------------------------------------------------------------
__global__ void __launch_bounds__(256, 2) proj_bf16_kernel(
    const __nv_bfloat16* __restrict__ h,
    const float* __restrict__ b0, const float* __restrict__ b1,
    const float* __restrict__ b2,
    __nv_bfloat16* __restrict__ q16, __nv_bfloat16* __restrict__ k16,
    __half* __restrict__ v16h)
{
    int pt = blockIdx.x;
    int e  = blockIdx.y;
    int b  = blockIdx.z / 3, pr = blockIdx.z % 3;

    const __nv_bfloat16* Wb; const float* bias; const __nv_bfloat16* cond;
    if (pr == 0) { Wb = g_w0b; bias = b0; cond = g_qcb + (size_t)(b>>1)*COND_*HW_; }
    else {
        cond = (((b & 1) ? g_kbb : g_kab)) + (size_t)(b>>1)*COND_*HW_;
        if (pr == 1) { Wb = g_w1b; bias = b1; }
        else         { Wb = g_w2b; bias = b2; }
    }
    const __nv_bfloat16* hb = h + (size_t)b*C_*HW_;

    __shared__ __nv_bfloat16 Xs[2][32*136];
    __shared__ __nv_bfloat16 Ws[2][32*136];
    const uint32_t xs_base0 = smem_u32(&Xs[0][0]);
    const uint32_t xs_base1 = smem_u32(&Xs[1][0]);
    const uint32_t ws_base0 = smem_u32(&Ws[0][0]);
    const uint32_t ws_base1 = smem_u32(&Ws[1][0]);

    const int tid  = threadIdx.x;
    const int warp = tid >> 5;
    const int lane = tid & 31;
    const int g    = lane >> 2;
    const int t    = lane & 3;
    const int q0   = warp * 16;

    const int arow = (lane & 7) + ((lane >> 4) & 1)*8;
    const int acol = q0 + ((lane >> 3) & 1)*8;
    const int brow = (lane & 7) + ((lane >> 3) & 1)*8;
    const int bcol = (lane >> 4)*8;

    auto stage = [&](int ch, int st) {
        uint32_t xd = st ? xs_base1 : xs_base0;
        uint32_t wd = st ? ws_base1 : ws_base0;
        const __nv_bfloat16* xsrc = (ch < 4) ? (hb + (size_t)(ch*32)*HW_ + pt*128)
                                             : (cond + pt*128);
        const __nv_bfloat16* wsrc = Wb + (size_t)(ch*32)*512 + e*128;
        #pragma unroll
        for (int it = 0; it < 2; it++) {
            int idx = it*256 + tid;
            int r = idx >> 4, c8 = idx & 15;
            cp_async16(xd + (uint32_t)(r*136 + c8*8)*2, xsrc + (size_t)r*HW_ + c8*8);
            cp_async16(wd + (uint32_t)(r*136 + c8*8)*2, wsrc + (size_t)r*512 + c8*8);
        }
    };

    float o[16][4];
    #pragma unroll
    for (int ct = 0; ct < 16; ct++)
        #pragma unroll
        for (int j = 0; j < 4; j++) o[ct][j] = 0.f;

    stage(0, 0); CP_COMMIT();

    for (int ch = 0; ch < 5; ch++) {
        int cur = ch & 1;
        if (ch < 4) { stage(ch + 1, cur ^ 1); CP_COMMIT(); CP_WAIT1(); }
        else        { CP_WAIT0(); }
        __syncthreads();

        uint32_t xb = cur ? xs_base1 : xs_base0;
        uint32_t wb2 = cur ? ws_base1 : ws_base0;
        uint32_t a[2][4];
        #pragma unroll
        for (int ks = 0; ks < 2; ks++)
            ldsm_x4t(a[ks], xb + (uint32_t)((ks*16 + arow)*136 + acol)*2);
        #pragma unroll
        for (int ks = 0; ks < 2; ks++) {
            #pragma unroll
            for (int u = 0; u < 8; u++) {
                uint32_t bf[4];
                ldsm_x4t(bf, wb2 + (uint32_t)((ks*16 + brow)*136 + u*16 + bcol)*2);
                mma_bf16(o[2*u],   a[ks], bf[0], bf[1]);
                mma_bf16(o[2*u+1], a[ks], bf[2], bf[3]);
            }
        }
        __syncthreads();
    }

    int s_row = pt*128 + q0 + g;
    if (pr == 2) {
        __half* dst = v16h + (size_t)(b*NH_ + e)*HW_*C_;
        #pragma unroll
        for (int ct = 0; ct < 16; ct++) {
            int c = ct*8 + 2*t;
            float bL = bias[e*128 + c], bH = bias[e*128 + c + 1];
            *(uint32_t*)&dst[(size_t)s_row*C_ + c]       = pack_f16(o[ct][0] + bL, o[ct][1] + bH);
            *(uint32_t*)&dst[(size_t)(s_row + 8)*C_ + c] = pack_f16(o[ct][2] + bL, o[ct][3] + bH);
        }
    } else {
        __nv_bfloat16* dst = (pr == 0 ? q16 : k16) + (size_t)(b*NH_ + e)*HW_*C_;
        #pragma unroll
        for (int ct = 0; ct < 16; ct++) {
            int c = ct*8 + 2*t;
            float bL = bias[e*128 + c], bH = bias[e*128 + c + 1];
            *(uint32_t*)&dst[(size_t)s_row*C_ + c]       = pack_bf16(o[ct][0] + bL, o[ct][1] + bH);
            *(uint32_t*)&dst[(size_t)(s_row + 8)*C_ + c] = pack_bf16(o[ct][2] + bL, o[ct][3] + bH);
        }
    }
}

// ---------------------------------------------------------------------------
// Attention: QK bf16 f32-accum; PV fp16 f16-accum (2x rate path), flushed to
// fp32 every 16 keys. P scaled by 2^-8 inside ex2 (cancels in o/l).
// 8 warps x 16 rows, 2-stage ring, 1 CTA/SM (reg budget 255).
// ---------------------------------------------------------------------------
#define PAD16 136
#define KVBUF 17408
#define ATTN_SMEM 69632

__global__ void __launch_bounds__(256, 1) attn_bf16_kernel(
    const __nv_bfloat16* __restrict__ gq, const __nv_bfloat16* __restrict__ gk,
    const __half* __restrict__ gv, __nv_bfloat16* __restrict__ hh)
{
    extern __shared__ char smraw[];
    __nv_bfloat16* qsm = (__nv_bfloat16*)smraw;
    float*         osm = (float*)smraw;
    const uint32_t smbase = smem_u32(smraw);

    const int tid  = threadIdx.x;
    const int warp = tid >> 5;
    const int lane = tid & 31;
    const int g    = lane >> 2;
    const int t    = lane & 3;
    const int q0   = warp * 16;

    int qt = blockIdx.x;
    int z  = blockIdx.y;
    int e  = z & 3, s5 = (z >> 2) % 6, b4 = z / 24;
    const int qtab[6] = {0,1,2,3,0,2};
    const int ktab[6] = {1,0,3,2,2,0};

    const __nv_bfloat16* qsrc = gq + (size_t)((b4*4 + qtab[s5])*NH_ + e)*(HW_*C_)
                                   + (size_t)qt*128*C_;
    const __nv_bfloat16* ksrc = gk + (size_t)((b4*4 + ktab[s5])*NH_ + e)*(HW_*C_);
    const __half*        vsrc = gv + (size_t)((b4*4 + ktab[s5])*NH_ + e)*(HW_*C_);
    int idx0 = s5*512 + e*128;
    __nv_bfloat16* out = hh + ((size_t)(b4*4 + idx0/768)*768 + (idx0 % 768)) * HW_;

    #pragma unroll
    for (int it = 0; it < 8; it++) {
        int idx = it*256 + tid;
        int r = idx >> 4, c8 = idx & 15;
        *(uint4*)&qsm[r*PAD16 + c8*8] = *(const uint4*)(qsrc + (size_t)r*C_ + c8*8);
    }
    __syncthreads();
    uint32_t qa[8][4];
    {
        int row = q0 + (lane & 7) + ((lane >> 3) & 1)*8;
        int cof = (lane >> 4)*8;
        #pragma unroll
        for (int ks = 0; ks < 8; ks++)
            ldsm_x4(qa[ks], smbase + (uint32_t)(row*PAD16 + ks*16 + cof)*2);
    }
    __syncthreads();

    auto stage_kv = [&](int kt, int st) {
        const __nv_bfloat16* kc = ksrc + (size_t)(kt*64)*C_;
        const __half*        vc = vsrc + (size_t)(kt*64)*C_;
        uint32_t kd = smbase + st*KVBUF;
        uint32_t vd = smbase + (2 + st)*KVBUF;
        #pragma unroll
        for (int it = 0; it < 4; it++) {
            int idx = it*256 + tid;
            int r = idx >> 4, c8 = idx & 15;
            cp_async16(kd + (uint32_t)(r*PAD16 + c8*8)*2, kc + (size_t)r*C_ + c8*8);
            cp_async16(vd + (uint32_t)(r*PAD16 + c8*8)*2, vc + (size_t)r*C_ + c8*8);
        }
    };

    float o32[16][4];
    #pragma unroll
    for (int ct = 0; ct < 16; ct++)
        #pragma unroll
        for (int j = 0; j < 4; j++) o32[ct][j] = 0.f;
    float l0 = 0.f, l1 = 0.f;
    const float K2 = 0.08838834764831845f * 1.4426950408889634f;

    const int krow_lo = (lane & 7);
    const int kcol    = (lane >> 3)*8;
    const int vrow    = (lane & 7) + ((lane >> 3) & 1)*8;
    const int vcol    = (lane >> 4)*8;

    stage_kv(0, 0); CP_COMMIT();

    for (int kt = 0; kt < 16; kt++) {
        int cur = kt & 1;
        if (kt < 15) { stage_kv(kt + 1, cur ^ 1); CP_COMMIT(); CP_WAIT1(); }
        else         { CP_WAIT0(); }
        __syncthreads();

        uint32_t kb2 = smbase + cur*KVBUF;
        uint32_t vb2 = smbase + (2 + cur)*KVBUF;

        #pragma unroll
        for (int j = 0; j < 4; j++) {
            float ca[4] = {0.f,0.f,0.f,0.f};
            float cb[4] = {0.f,0.f,0.f,0.f};
            #pragma unroll
            for (int kbk = 0; kbk < 4; kbk++) {
                uint32_t kfa[4], kfb[4];
                ldsm_x4(kfa, kb2 + (uint32_t)(((2*j)*8 + krow_lo)*PAD16 + kbk*32 + kcol)*2);
                ldsm_x4(kfb, kb2 + (uint32_t)(((2*j+1)*8 + krow_lo)*PAD16 + kbk*32 + kcol)*2);
                mma_bf16(ca, qa[2*kbk],   kfa[0], kfa[1]);
                mma_bf16(ca, qa[2*kbk+1], kfa[2], kfa[3]);
                mma_bf16(cb, qa[2*kbk],   kfb[0], kfb[1]);
                mma_bf16(cb, qa[2*kbk+1], kfb[2], kfb[3]);
            }

            // exp with 2^-8 scaling baked into the exponent (cancels in o/l)
            float pa0 = fast_ex2(ca[0]*K2 - 8.f), pa1 = fast_ex2(ca[1]*K2 - 8.f);
            float pa2 = fast_ex2(ca[2]*K2 - 8.f), pa3 = fast_ex2(ca[3]*K2 - 8.f);
            float pb0 = fast_ex2(cb[0]*K2 - 8.f), pb1 = fast_ex2(cb[1]*K2 - 8.f);
            float pb2 = fast_ex2(cb[2]*K2 - 8.f), pb3 = fast_ex2(cb[3]*K2 - 8.f);
            l0 += (pa0 + pa1) + (pb0 + pb1);
            l1 += (pa2 + pa3) + (pb2 + pb3);
            uint32_t pA[4];
            pA[0] = pack_f16(pa0, pa1);
            pA[1] = pack_f16(pa2, pa3);
            pA[2] = pack_f16(pb0, pb1);
            pA[3] = pack_f16(pb2, pb3);

            // PV with fp16 accumulators (16 keys), flushed below
            uint32_t o16[16][2];
            #pragma unroll
            for (int u2 = 0; u2 < 16; u2++) { o16[u2][0] = 0u; o16[u2][1] = 0u; }

            uint32_t vbase = vb2 + (uint32_t)((j*16 + vrow)*PAD16 + vcol)*2;
            #pragma unroll
            for (int u = 0; u < 8; u++) {
                uint32_t vf[4];
                ldsm_x4t(vf, vbase + (uint32_t)(u*16)*2);
                mma_f16acc(o16[2*u],   pA, vf[0], vf[1]);
                mma_f16acc(o16[2*u+1], pA, vf[2], vf[3]);
            }
            // flush fp16 partials to fp32
            #pragma unroll
            for (int u2 = 0; u2 < 16; u2++) {
                float2 lo = __half22float2(*(__half2*)&o16[u2][0]);
                float2 hi = __half22float2(*(__half2*)&o16[u2][1]);
                o32[u2][0] += lo.x; o32[u2][1] += lo.y;
                o32[u2][2] += hi.x; o32[u2][3] += hi.y;
            }
        }
        __syncthreads();
    }

    l0 += __shfl_xor_sync(~0u, l0, 1);
    l0 += __shfl_xor_sync(~0u, l0, 2);
    l1 += __shfl_xor_sync(~0u, l1, 1);
    l1 += __shfl_xor_sync(~0u, l1, 2);
    float inv0 = 1.f / l0, inv1 = 1.f / l1;

    #pragma unroll
    for (int ct = 0; ct < 16; ct++) {
        int c = ct*8 + 2*t;
        *(float2*)&osm[(q0 + g)*132 + c]     = make_float2(o32[ct][0]*inv0, o32[ct][1]*inv0);
        *(float2*)&osm[(q0 + g + 8)*132 + c] = make_float2(o32[ct][2]*inv1, o32[ct][3]*inv1);
    }
    __syncthreads();
    #pragma unroll
    for (int it = 0; it < 32; it++) {
        int idx = it*256 + tid;
        int c = idx >> 6, qp = idx & 63;
        uint32_t pk = pack_bf16(osm[(2*qp)*132 + c], osm[(2*qp + 1)*132 + c]);
        *(uint32_t*)&out[(size_t)c*HW_ + qt*128 + 2*qp] = pk;
    }
}

// ---------------------------------------------------------------------------
// Output projection (R10 best config: N=128, K=64, grid 128, 2-stage)
// ---------------------------------------------------------------------------
__global__ void __launch_bounds__(256) out_bf16_kernel(
    const __nv_bfloat16* __restrict__ hh, const float* __restrict__ b3,
    const float* __restrict__ x, float* __restrict__ out)
{
    extern __shared__ __nv_bfloat16 sm2[];
    const uint32_t base = smem_u32(sm2);

    int pt = blockIdx.x;
    int b  = blockIdx.y;
    const __nv_bfloat16* hb = hh + (size_t)b*768*HW_;

    const int tid  = threadIdx.x;
    const int warp = tid >> 5;
    const int lane = tid & 31;
    const int g    = lane >> 2;
    const int t    = lane & 3;
    const int q0   = warp * 16;

    const int arow = (lane & 7) + ((lane >> 4) & 1)*8;
    const int acol = q0 + ((lane >> 3) & 1)*8;
    const int brow = (lane & 7) + ((lane >> 3) & 1)*8;
    const int bcol = (lane >> 4)*8;

    auto stage = [&](int kc, int st) {
        uint32_t ad = base + (uint32_t)(st*8704)*2;
        uint32_t bd = base + (uint32_t)((2 + st)*8704)*2;
        const __nv_bfloat16* asrc = g_w3b + (size_t)(kc*64)*128;
        const __nv_bfloat16* bsrc = hb + (size_t)(kc*64)*HW_ + pt*128;
        #pragma unroll
        for (int it = 0; it < 4; it++) {
            int idx = it*256 + tid;
            int r = idx >> 4, c8 = idx & 15;
            cp_async16(ad + (uint32_t)(r*136 + c8*8)*2, asrc + (size_t)r*128 + c8*8);
            cp_async16(bd + (uint32_t)(r*136 + c8*8)*2, bsrc + (size_t)r*HW_ + c8*8);
        }
    };

    float o[16][4];
    #pragma unroll
    for (int ct = 0; ct < 16; ct++)
        #pragma unroll
        for (int j = 0; j < 4; j++) o[ct][j] = 0.f;

    stage(0, 0); CP_COMMIT();

    for (int kc = 0; kc < 12; kc++) {
        int cur = kc & 1;
        if (kc < 11) { stage(kc + 1, cur ^ 1); CP_COMMIT(); CP_WAIT1(); }
        else         { CP_WAIT0(); }
        __syncthreads();

        uint32_t ab = base + (uint32_t)(cur*8704)*2;
        uint32_t bb = base + (uint32_t)((2 + cur)*8704)*2;

        uint32_t a[4][4];
        #pragma unroll
        for (int ks = 0; ks < 4; ks++)
            ldsm_x4t(a[ks], ab + (uint32_t)((ks*16 + arow)*136 + acol)*2);
        #pragma unroll
        for (int ks = 0; ks < 4; ks++) {
            #pragma unroll
            for (int u = 0; u < 8; u++) {
                uint32_t bf[4];
                ldsm_x4t(bf, bb + (uint32_t)((ks*16 + brow)*136 + u*16 + bcol)*2);
                mma_bf16(o[2*u],   a[ks], bf[0], bf[1]);
                mma_bf16(o[2*u+1], a[ks], bf[2], bf[3]);
            }
        }
        __syncthreads();
    }

    float bb0 = b3[q0 + g];
    float bb1 = b3[q0 + g + 8];
    #pragma unroll
    for (int ct = 0; ct < 16; ct++) {
        size_t a0 = ((size_t)b*C_ + q0 + g)*HW_ + pt*128 + ct*8 + 2*t;
        size_t a1 = ((size_t)b*C_ + q0 + g + 8)*HW_ + pt*128 + ct*8 + 2*t;
        float2 x0 = *(const float2*)&x[a0];
        float2 x1 = *(const float2*)&x[a1];
        *(float2*)&out[a0] = make_float2(o[ct][0] + bb0 + x0.x, o[ct][1] + bb0 + x0.y);
        *(float2*)&out[a1] = make_float2(o[ct][2] + bb1 + x1.x, o[ct][3] + bb1 + x1.y);
    }
}

// ---------------------------------------------------------------------------
extern "C" void kernel_launch(void* const* d_in, const int* in_sizes, int n_in,
                              void* d_out, int out_size)
{
    const float* x      = (const float*)d_in[0];
    const float* q_cond = (const float*)d_in[1];
    const float* ka     = (const float*)d_in[2];
    const float* kb     = (const float*)d_in[3];
    const float* gs     = (const float*)d_in[4];
    const float* gb     = (const float*)d_in[5];
    const float* W0 = (const float*)d_in[6];  const float* b0 = (const float*)d_in[7];
    const float* W1 = (const float*)d_in[8];  const float* b1 = (const float*)d_in[9];
    const float* W2 = (const float*)d_in[10]; const float* b2 = (const float*)d_in[11];
    const float* W3 = (const float*)d_in[12]; const float* b3 = (const float*)d_in[13];
    float* out = (float*)d_out;

    __nv_bfloat16 *h16, *q16, *k16, *hh16;
    __half *v16h;
    cudaGetSymbolAddress((void**)&h16,  g_h16);
    cudaGetSymbolAddress((void**)&q16,  g_q16);
    cudaGetSymbolAddress((void**)&k16,  g_k16);
    cudaGetSymbolAddress((void**)&v16h, g_v16h);
    cudaGetSymbolAddress((void**)&hh16, g_hh16);

    cudaFuncSetAttribute(attn_bf16_kernel,
                         cudaFuncAttributeMaxDynamicSharedMemorySize, ATTN_SMEM);
    const int out_smem = 4 * 8704 * 2;  // 69632 B
    cudaFuncSetAttribute(out_bf16_kernel,
                         cudaFuncAttributeMaxDynamicSharedMemorySize, out_smem);

    gncvt_kernel<<<1616, 256>>>(x, gs, gb, h16, W0, W1, W2, W3, q_cond, ka, kb);

    dim3 pg(8, 4, 48);
    proj_bf16_kernel<<<pg, 256>>>(h16, b0, b1, b2, q16, k16, v16h);

    dim3 ag(8, 96);
    attn_bf16_kernel<<<ag, 256, ATTN_SMEM>>>(q16, k16, v16h, hh16);

    dim3 og(8, 16);
    out_bf16_kernel<<<og, 256, out_smem>>>(hh16, b3, x, out);
}

// round 15
// speedup vs baseline: 1.3415x; 1.3415x over previous
#include <cuda_runtime.h>
#include <cuda_bf16.h>
#include <cstdint>

#define B_   16
#define C_   128
#define HW_  1024
#define NH_  4
#define COND_ 32

// Scratch (device globals; no allocations allowed)
__device__ __nv_bfloat16  g_h16 [B_*C_*HW_];
__device__ __nv_bfloat16  g_q16 [B_*NH_*HW_*C_];
__device__ __nv_bfloat16  g_k16 [B_*NH_*HW_*C_];
__device__ __nv_bfloat16  g_v16 [B_*NH_*HW_*C_];
__device__ __nv_bfloat16  g_hh16[B_*6*C_*HW_];
__device__ __nv_bfloat16  g_w0b[160*512];
__device__ __nv_bfloat16  g_w1b[160*512];
__device__ __nv_bfloat16  g_w2b[160*512];
__device__ __nv_bfloat16  g_w3b[768*128];
__device__ __nv_bfloat16  g_qcb[(B_/2)*COND_*HW_];
__device__ __nv_bfloat16  g_kab[(B_/2)*COND_*HW_];
__device__ __nv_bfloat16  g_kbb[(B_/2)*COND_*HW_];

// ---------------------------------------------------------------------------
__device__ __forceinline__ uint32_t smem_u32(const void* p) {
    uint32_t a;
    asm("{ .reg .u64 t; cvta.to.shared.u64 t, %1; cvt.u32.u64 %0, t; }"
        : "=r"(a) : "l"(p));
    return a;
}
__device__ __forceinline__ uint32_t pack_bf16(float lo, float hi) {
    uint32_t r;
    asm("cvt.rn.bf16x2.f32 %0, %1, %2;" : "=r"(r) : "f"(hi), "f"(lo));
    return r;
}
__device__ __forceinline__ float fast_ex2(float x) {
    float y;
    asm("ex2.approx.f32 %0, %1;" : "=f"(y) : "f"(x));
    return y;
}
__device__ __forceinline__ void mma_bf16(float c[4], const uint32_t a[4],
                                         uint32_t b0, uint32_t b1) {
    asm volatile("mma.sync.aligned.m16n8k16.row.col.f32.bf16.bf16.f32 "
        "{%0,%1,%2,%3}, {%4,%5,%6,%7}, {%8,%9}, {%0,%1,%2,%3};"
        : "+f"(c[0]), "+f"(c[1]), "+f"(c[2]), "+f"(c[3])
        : "r"(a[0]), "r"(a[1]), "r"(a[2]), "r"(a[3]), "r"(b0), "r"(b1));
}
__device__ __forceinline__ void ldsm_x4(uint32_t r[4], uint32_t addr) {
    asm volatile("ldmatrix.sync.aligned.m8n8.x4.shared.b16 {%0,%1,%2,%3}, [%4];"
        : "=r"(r[0]), "=r"(r[1]), "=r"(r[2]), "=r"(r[3]) : "r"(addr));
}
__device__ __forceinline__ void ldsm_x4t(uint32_t r[4], uint32_t addr) {
    asm volatile("ldmatrix.sync.aligned.m8n8.x4.trans.shared.b16 {%0,%1,%2,%3}, [%4];"
        : "=r"(r[0]), "=r"(r[1]), "=r"(r[2]), "=r"(r[3]) : "r"(addr));
}
__device__ __forceinline__ void cp_async16(uint32_t dst, const void* src) {
    asm volatile("cp.async.cg.shared.global [%0], [%1], 16;"
                 :: "r"(dst), "l"(src) : "memory");
}
#define CP_COMMIT() asm volatile("cp.async.commit_group;" ::: "memory")
#define CP_WAIT1()  asm volatile("cp.async.wait_group 1;" ::: "memory")
#define CP_WAIT0()  asm volatile("cp.async.wait_group 0;" ::: "memory")

// ---------------------------------------------------------------------------
// Fused GroupNorm (blocks 0..511) + fp32->bf16 convert (blocks 512+)
// ---------------------------------------------------------------------------
__global__ void __launch_bounds__(256) gncvt_kernel(
    const float* __restrict__ x, const float* __restrict__ scale,
    const float* __restrict__ bias, __nv_bfloat16* __restrict__ h,
    const float* __restrict__ W0, const float* __restrict__ W1,
    const float* __restrict__ W2, const float* __restrict__ W3,
    const float* __restrict__ qc, const float* __restrict__ ka,
    const float* __restrict__ kb)
{
    int blk = blockIdx.x;
    if (blk >= 512) {
        int j = blk - 512;
        const float* src; __nv_bfloat16* dst; int base;
        if      (j < 80)   { src = W0; dst = g_w0b; base = j; }
        else if (j < 160)  { src = W1; dst = g_w1b; base = j - 80; }
        else if (j < 240)  { src = W2; dst = g_w2b; base = j - 160; }
        else if (j < 336)  { src = W3; dst = g_w3b; base = j - 240; }
        else if (j < 592)  { src = qc; dst = g_qcb; base = j - 336; }
        else if (j < 848)  { src = ka; dst = g_kab; base = j - 592; }
        else               { src = kb; dst = g_kbb; base = j - 848; }
        int i = base*1024 + threadIdx.x*4;
        float4 v = *(const float4*)&src[i];
        *(uint2*)&dst[i] = make_uint2(pack_bf16(v.x, v.y), pack_bf16(v.z, v.w));
        return;
    }

    int b = blk >> 5, grp = blk & 31;
    const float* xp = x + (size_t)(b*C_ + grp*4)*HW_;
    __nv_bfloat16* hp = h + (size_t)(b*C_ + grp*4)*HW_;

    float v[16];
    float s = 0.f, ss = 0.f;
    #pragma unroll
    for (int it = 0; it < 4; it++) {
        int i = (it*256 + threadIdx.x)*4;
        float4 q = *(const float4*)&xp[i];
        v[it*4+0] = q.x; v[it*4+1] = q.y; v[it*4+2] = q.z; v[it*4+3] = q.w;
        s  += (q.x + q.y) + (q.z + q.w);
        ss += (q.x*q.x + q.y*q.y) + (q.z*q.z + q.w*q.w);
    }
    #pragma unroll
    for (int o = 16; o; o >>= 1) {
        s  += __shfl_xor_sync(~0u, s,  o);
        ss += __shfl_xor_sync(~0u, ss, o);
    }
    __shared__ float sh_s[8], sh_ss[8];
    int w = threadIdx.x >> 5;
    if ((threadIdx.x & 31) == 0) { sh_s[w] = s; sh_ss[w] = ss; }
    __syncthreads();
    if (threadIdx.x < 32) {
        s  = (threadIdx.x < 8) ? sh_s [threadIdx.x] : 0.f;
        ss = (threadIdx.x < 8) ? sh_ss[threadIdx.x] : 0.f;
        #pragma unroll
        for (int o = 4; o; o >>= 1) {
            s  += __shfl_xor_sync(~0u, s,  o);
            ss += __shfl_xor_sync(~0u, ss, o);
        }
        if (threadIdx.x == 0) { sh_s[0] = s; sh_ss[0] = ss; }
    }
    __syncthreads();
    float mean = sh_s[0] * (1.f/4096.f);
    float var  = sh_ss[0] * (1.f/4096.f) - mean*mean;
    float inv  = rsqrtf(var + 1e-6f);
    #pragma unroll
    for (int it = 0; it < 4; it++) {
        int i = (it*256 + threadIdx.x)*4;
        int c = grp*4 + (i >> 10);
        float sc = scale[c]*inv, bi = bias[c] - mean*scale[c]*inv;
        uint2 pk = make_uint2(pack_bf16(v[it*4+0]*sc + bi, v[it*4+1]*sc + bi),
                              pack_bf16(v[it*4+2]*sc + bi, v[it*4+3]*sc + bi));
        *(uint2*)&hp[i] = pk;
    }
}

// ---------------------------------------------------------------------------
// QKV projection (R12 version)
// ---------------------------------------------------------------------------
__global__ void __launch_bounds__(256, 2) proj_bf16_kernel(
    const __nv_bfloat16* __restrict__ h,
    const float* __restrict__ b0, const float* __restrict__ b1,
    const float* __restrict__ b2,
    __nv_bfloat16* __restrict__ q16, __nv_bfloat16* __restrict__ k16,
    __nv_bfloat16* __restrict__ v16)
{
    int pt = blockIdx.x;
    int e  = blockIdx.y;
    int b  = blockIdx.z / 3, pr = blockIdx.z % 3;

    const __nv_bfloat16* Wb; const float* bias; const __nv_bfloat16* cond;
    __nv_bfloat16* dstb;
    if (pr == 0) { Wb = g_w0b; bias = b0; dstb = q16; cond = g_qcb + (size_t)(b>>1)*COND_*HW_; }
    else {
        cond = (((b & 1) ? g_kbb : g_kab)) + (size_t)(b>>1)*COND_*HW_;
        if (pr == 1) { Wb = g_w1b; bias = b1; dstb = k16; }
        else         { Wb = g_w2b; bias = b2; dstb = v16; }
    }
    const __nv_bfloat16* hb = h + (size_t)b*C_*HW_;
    __nv_bfloat16* dst = dstb + (size_t)(b*NH_ + e)*HW_*C_;

    __shared__ __nv_bfloat16 Xs[2][32*136];
    __shared__ __nv_bfloat16 Ws[2][32*136];
    const uint32_t xs_base0 = smem_u32(&Xs[0][0]);
    const uint32_t xs_base1 = smem_u32(&Xs[1][0]);
    const uint32_t ws_base0 = smem_u32(&Ws[0][0]);
    const uint32_t ws_base1 = smem_u32(&Ws[1][0]);

    const int tid  = threadIdx.x;
    const int warp = tid >> 5;
    const int lane = tid & 31;
    const int g    = lane >> 2;
    const int t    = lane & 3;
    const int q0   = warp * 16;

    const int arow = (lane & 7) + ((lane >> 4) & 1)*8;
    const int acol = q0 + ((lane >> 3) & 1)*8;
    const int brow = (lane & 7) + ((lane >> 3) & 1)*8;
    const int bcol = (lane >> 4)*8;

    auto stage = [&](int ch, int st) {
        uint32_t xd = st ? xs_base1 : xs_base0;
        uint32_t wd = st ? ws_base1 : ws_base0;
        const __nv_bfloat16* xsrc = (ch < 4) ? (hb + (size_t)(ch*32)*HW_ + pt*128)
                                             : (cond + pt*128);
        const __nv_bfloat16* wsrc = Wb + (size_t)(ch*32)*512 + e*128;
        #pragma unroll
        for (int it = 0; it < 2; it++) {
            int idx = it*256 + tid;
            int r = idx >> 4, c8 = idx & 15;
            cp_async16(xd + (uint32_t)(r*136 + c8*8)*2, xsrc + (size_t)r*HW_ + c8*8);
            cp_async16(wd + (uint32_t)(r*136 + c8*8)*2, wsrc + (size_t)r*512 + c8*8);
        }
    };

    float o[16][4];
    #pragma unroll
    for (int ct = 0; ct < 16; ct++)
        #pragma unroll
        for (int j = 0; j < 4; j++) o[ct][j] = 0.f;

    stage(0, 0); CP_COMMIT();

    for (int ch = 0; ch < 5; ch++) {
        int cur = ch & 1;
        if (ch < 4) { stage(ch + 1, cur ^ 1); CP_COMMIT(); CP_WAIT1(); }
        else        { CP_WAIT0(); }
        __syncthreads();

        uint32_t xb = cur ? xs_base1 : xs_base0;
        uint32_t wb2 = cur ? ws_base1 : ws_base0;
        uint32_t a[2][4];
        #pragma unroll
        for (int ks = 0; ks < 2; ks++)
            ldsm_x4t(a[ks], xb + (uint32_t)((ks*16 + arow)*136 + acol)*2);
        #pragma unroll
        for (int ks = 0; ks < 2; ks++) {
            #pragma unroll
            for (int u = 0; u < 8; u++) {
                uint32_t bf[4];
                ldsm_x4t(bf, wb2 + (uint32_t)((ks*16 + brow)*136 + u*16 + bcol)*2);
                mma_bf16(o[2*u],   a[ks], bf[0], bf[1]);
                mma_bf16(o[2*u+1], a[ks], bf[2], bf[3]);
            }
        }
        __syncthreads();
    }

    int s_row = pt*128 + q0 + g;
    #pragma unroll
    for (int ct = 0; ct < 16; ct++) {
        int c = ct*8 + 2*t;
        float bL = bias[e*128 + c], bH = bias[e*128 + c + 1];
        *(uint32_t*)&dst[(size_t)s_row*C_ + c]       = pack_bf16(o[ct][0] + bL, o[ct][1] + bH);
        *(uint32_t*)&dst[(size_t)(s_row + 8)*C_ + c] = pack_bf16(o[ct][2] + bL, o[ct][3] + bH);
    }
}

// ---------------------------------------------------------------------------
// Attention (R12 best config) + cp.async prologue overlap:
// K0/V0 issued first; Q staged via cp.async into the K1/V1 buffers
// (rows 0-63 -> K1 region, rows 64-127 -> V1 region), overlapping fetches.
// ---------------------------------------------------------------------------
#define PAD16 136
#define KVBUF 17408
#define ATTN_SMEM 69632

__global__ void __launch_bounds__(256, 2) attn_bf16_kernel(
    const __nv_bfloat16* __restrict__ gq, const __nv_bfloat16* __restrict__ gk,
    const __nv_bfloat16* __restrict__ gv, __nv_bfloat16* __restrict__ hh)
{
    extern __shared__ char smraw[];
    float* osm = (float*)smraw;
    const uint32_t smbase = smem_u32(smraw);

    const int tid  = threadIdx.x;
    const int warp = tid >> 5;
    const int lane = tid & 31;
    const int g    = lane >> 2;
    const int t    = lane & 3;
    const int q0   = warp * 16;

    int qt = blockIdx.x;
    int z  = blockIdx.y;
    int e  = z & 3, s5 = (z >> 2) % 6, b4 = z / 24;
    const int qtab[6] = {0,1,2,3,0,2};
    const int ktab[6] = {1,0,3,2,2,0};

    const __nv_bfloat16* qsrc = gq + (size_t)((b4*4 + qtab[s5])*NH_ + e)*(HW_*C_)
                                   + (size_t)qt*128*C_;
    const __nv_bfloat16* ksrc = gk + (size_t)((b4*4 + ktab[s5])*NH_ + e)*(HW_*C_);
    const __nv_bfloat16* vsrc = gv + (size_t)((b4*4 + ktab[s5])*NH_ + e)*(HW_*C_);
    int idx0 = s5*512 + e*128;
    __nv_bfloat16* out = hh + ((size_t)(b4*4 + idx0/768)*768 + (idx0 % 768)) * HW_;

    auto stage_kv = [&](int kt, int st) {
        const __nv_bfloat16* kc = ksrc + (size_t)(kt*64)*C_;
        const __nv_bfloat16* vc = vsrc + (size_t)(kt*64)*C_;
        uint32_t kd = smbase + st*KVBUF;
        uint32_t vd = smbase + (2 + st)*KVBUF;
        #pragma unroll
        for (int it = 0; it < 4; it++) {
            int idx = it*256 + tid;
            int r = idx >> 4, c8 = idx & 15;
            cp_async16(kd + (uint32_t)(r*PAD16 + c8*8)*2, kc + (size_t)r*C_ + c8*8);
            cp_async16(vd + (uint32_t)(r*PAD16 + c8*8)*2, vc + (size_t)r*C_ + c8*8);
        }
    };

    // ---- prologue: K0/V0 first, Q into K1 (rows 0-63) + V1 (rows 64-127) ----
    stage_kv(0, 0); CP_COMMIT();
    {
        uint32_t qd0 = smbase + 1*KVBUF;   // K1 region: Q rows 0-63
        uint32_t qd1 = smbase + 3*KVBUF;   // V1 region: Q rows 64-127
        #pragma unroll
        for (int it = 0; it < 8; it++) {
            int idx = it*256 + tid;
            int r = idx >> 4, c8 = idx & 15;
            uint32_t dst = (r < 64) ? (qd0 + (uint32_t)(r*PAD16 + c8*8)*2)
                                    : (qd1 + (uint32_t)((r - 64)*PAD16 + c8*8)*2);
            cp_async16(dst, qsrc + (size_t)r*C_ + c8*8);
        }
        CP_COMMIT();
    }
    CP_WAIT0();
    __syncthreads();

    uint32_t qa[8][4];
    {
        int row = q0 + (lane & 7) + ((lane >> 3) & 1)*8;
        uint32_t qbase = (row < 64) ? (smbase + 1*KVBUF + (uint32_t)(row*PAD16)*2)
                                    : (smbase + 3*KVBUF + (uint32_t)((row - 64)*PAD16)*2);
        int cof = (lane >> 4)*8;
        #pragma unroll
        for (int ks = 0; ks < 8; ks++)
            ldsm_x4(qa[ks], qbase + (uint32_t)(ks*16 + cof)*2);
    }
    __syncthreads();   // Q regions free -> usable as K1/V1

    float o[16][4];
    #pragma unroll
    for (int ct = 0; ct < 16; ct++)
        #pragma unroll
        for (int j = 0; j < 4; j++) o[ct][j] = 0.f;
    float l0 = 0.f, l1 = 0.f;
    const float K2 = 0.08838834764831845f * 1.4426950408889634f;

    const int krow_lo = (lane & 7);
    const int kcol    = (lane >> 3)*8;
    const int vrow    = (lane & 7) + ((lane >> 3) & 1)*8;
    const int vcol    = (lane >> 4)*8;

    for (int kt = 0; kt < 16; kt++) {
        int cur = kt & 1;
        if (kt < 15) { stage_kv(kt + 1, cur ^ 1); CP_COMMIT(); CP_WAIT1(); }
        else         { CP_WAIT0(); }
        __syncthreads();

        uint32_t kb2 = smbase + cur*KVBUF;
        uint32_t vb2 = smbase + (2 + cur)*KVBUF;

        #pragma unroll
        for (int j = 0; j < 4; j++) {
            float ca[4] = {0.f,0.f,0.f,0.f}, caX[4] = {0.f,0.f,0.f,0.f};
            float cb[4] = {0.f,0.f,0.f,0.f}, cbX[4] = {0.f,0.f,0.f,0.f};
            #pragma unroll
            for (int kbk = 0; kbk < 4; kbk++) {
                uint32_t kfa[4], kfb[4];
                ldsm_x4(kfa, kb2 + (uint32_t)(((2*j)*8 + krow_lo)*PAD16 + kbk*32 + kcol)*2);
                ldsm_x4(kfb, kb2 + (uint32_t)(((2*j+1)*8 + krow_lo)*PAD16 + kbk*32 + kcol)*2);
                float* cA = (kbk < 2) ? ca : caX;
                float* cB = (kbk < 2) ? cb : cbX;
                mma_bf16((float(&)[4])*cA, qa[2*kbk],   kfa[0], kfa[1]);
                mma_bf16((float(&)[4])*cA, qa[2*kbk+1], kfa[2], kfa[3]);
                mma_bf16((float(&)[4])*cB, qa[2*kbk],   kfb[0], kfb[1]);
                mma_bf16((float(&)[4])*cB, qa[2*kbk+1], kfb[2], kfb[3]);
            }
            #pragma unroll
            for (int i = 0; i < 4; i++) { ca[i] += caX[i]; cb[i] += cbX[i]; }

            float pa0 = fast_ex2(ca[0]*K2), pa1 = fast_ex2(ca[1]*K2);
            float pa2 = fast_ex2(ca[2]*K2), pa3 = fast_ex2(ca[3]*K2);
            float pb0 = fast_ex2(cb[0]*K2), pb1 = fast_ex2(cb[1]*K2);
            float pb2 = fast_ex2(cb[2]*K2), pb3 = fast_ex2(cb[3]*K2);
            l0 += (pa0 + pa1) + (pb0 + pb1);
            l1 += (pa2 + pa3) + (pb2 + pb3);
            uint32_t pA[4];
            pA[0] = pack_bf16(pa0, pa1);
            pA[1] = pack_bf16(pa2, pa3);
            pA[2] = pack_bf16(pb0, pb1);
            pA[3] = pack_bf16(pb2, pb3);

            uint32_t vbase = vb2 + (uint32_t)((j*16 + vrow)*PAD16 + vcol)*2;
            #pragma unroll
            for (int u = 0; u < 8; u++) {
                uint32_t vf[4];
                ldsm_x4t(vf, vbase + (uint32_t)(u*16)*2);
                mma_bf16(o[2*u],   pA, vf[0], vf[1]);
                mma_bf16(o[2*u+1], pA, vf[2], vf[3]);
            }
        }
        __syncthreads();
    }

    l0 += __shfl_xor_sync(~0u, l0, 1);
    l0 += __shfl_xor_sync(~0u, l0, 2);
    l1 += __shfl_xor_sync(~0u, l1, 1);
    l1 += __shfl_xor_sync(~0u, l1, 2);
    float inv0 = 1.f / l0, inv1 = 1.f / l1;

    #pragma unroll
    for (int ct = 0; ct < 16; ct++) {
        int c = ct*8 + 2*t;
        *(float2*)&osm[(q0 + g)*132 + c]     = make_float2(o[ct][0]*inv0, o[ct][1]*inv0);
        *(float2*)&osm[(q0 + g + 8)*132 + c] = make_float2(o[ct][2]*inv1, o[ct][3]*inv1);
    }
    __syncthreads();
    #pragma unroll
    for (int it = 0; it < 32; it++) {
        int idx = it*256 + tid;
        int c = idx >> 6, qp = idx & 63;
        uint32_t pk = pack_bf16(osm[(2*qp)*132 + c], osm[(2*qp + 1)*132 + c]);
        *(uint32_t*)&out[(size_t)c*HW_ + qt*128 + 2*qp] = pk;
    }
}

// ---------------------------------------------------------------------------
// Output projection (R10 best config: N=128, K=64, grid 128, 2-stage)
// ---------------------------------------------------------------------------
__global__ void __launch_bounds__(256) out_bf16_kernel(
    const __nv_bfloat16* __restrict__ hh, const float* __restrict__ b3,
    const float* __restrict__ x, float* __restrict__ out)
{
    extern __shared__ __nv_bfloat16 sm2[];
    const uint32_t base = smem_u32(sm2);

    int pt = blockIdx.x;
    int b  = blockIdx.y;
    const __nv_bfloat16* hb = hh + (size_t)b*768*HW_;

    const int tid  = threadIdx.x;
    const int warp = tid >> 5;
    const int lane = tid & 31;
    const int g    = lane >> 2;
    const int t    = lane & 3;
    const int q0   = warp * 16;

    const int arow = (lane & 7) + ((lane >> 4) & 1)*8;
    const int acol = q0 + ((lane >> 3) & 1)*8;
    const int brow = (lane & 7) + ((lane >> 3) & 1)*8;
    const int bcol = (lane >> 4)*8;

    auto stage = [&](int kc, int st) {
        uint32_t ad = base + (uint32_t)(st*8704)*2;
        uint32_t bd = base + (uint32_t)((2 + st)*8704)*2;
        const __nv_bfloat16* asrc = g_w3b + (size_t)(kc*64)*128;
        const __nv_bfloat16* bsrc = hb + (size_t)(kc*64)*HW_ + pt*128;
        #pragma unroll
        for (int it = 0; it < 4; it++) {
            int idx = it*256 + tid;
            int r = idx >> 4, c8 = idx & 15;
            cp_async16(ad + (uint32_t)(r*136 + c8*8)*2, asrc + (size_t)r*128 + c8*8);
            cp_async16(bd + (uint32_t)(r*136 + c8*8)*2, bsrc + (size_t)r*HW_ + c8*8);
        }
    };

    float o[16][4];
    #pragma unroll
    for (int ct = 0; ct < 16; ct++)
        #pragma unroll
        for (int j = 0; j < 4; j++) o[ct][j] = 0.f;

    stage(0, 0); CP_COMMIT();

    for (int kc = 0; kc < 12; kc++) {
        int cur = kc & 1;
        if (kc < 11) { stage(kc + 1, cur ^ 1); CP_COMMIT(); CP_WAIT1(); }
        else         { CP_WAIT0(); }
        __syncthreads();

        uint32_t ab = base + (uint32_t)(cur*8704)*2;
        uint32_t bb = base + (uint32_t)((2 + cur)*8704)*2;

        uint32_t a[4][4];
        #pragma unroll
        for (int ks = 0; ks < 4; ks++)
            ldsm_x4t(a[ks], ab + (uint32_t)((ks*16 + arow)*136 + acol)*2);
        #pragma unroll
        for (int ks = 0; ks < 4; ks++) {
            #pragma unroll
            for (int u = 0; u < 8; u++) {
                uint32_t bf[4];
                ldsm_x4t(bf, bb + (uint32_t)((ks*16 + brow)*136 + u*16 + bcol)*2);
                mma_bf16(o[2*u],   a[ks], bf[0], bf[1]);
                mma_bf16(o[2*u+1], a[ks], bf[2], bf[3]);
            }
        }
        __syncthreads();
    }

    float bb0 = b3[q0 + g];
    float bb1 = b3[q0 + g + 8];
    #pragma unroll
    for (int ct = 0; ct < 16; ct++) {
        size_t a0 = ((size_t)b*C_ + q0 + g)*HW_ + pt*128 + ct*8 + 2*t;
        size_t a1 = ((size_t)b*C_ + q0 + g + 8)*HW_ + pt*128 + ct*8 + 2*t;
        float2 x0 = *(const float2*)&x[a0];
        float2 x1 = *(const float2*)&x[a1];
        *(float2*)&out[a0] = make_float2(o[ct][0] + bb0 + x0.x, o[ct][1] + bb0 + x0.y);
        *(float2*)&out[a1] = make_float2(o[ct][2] + bb1 + x1.x, o[ct][3] + bb1 + x1.y);
    }
}

// ---------------------------------------------------------------------------
extern "C" void kernel_launch(void* const* d_in, const int* in_sizes, int n_in,
                              void* d_out, int out_size)
{
    const float* x      = (const float*)d_in[0];
    const float* q_cond = (const float*)d_in[1];
    const float* ka     = (const float*)d_in[2];
    const float* kb     = (const float*)d_in[3];
    const float* gs     = (const float*)d_in[4];
    const float* gb     = (const float*)d_in[5];
    const float* W0 = (const float*)d_in[6];  const float* b0 = (const float*)d_in[7];
    const float* W1 = (const float*)d_in[8];  const float* b1 = (const float*)d_in[9];
    const float* W2 = (const float*)d_in[10]; const float* b2 = (const float*)d_in[11];
    const float* W3 = (const float*)d_in[12]; const float* b3 = (const float*)d_in[13];
    float* out = (float*)d_out;

    __nv_bfloat16 *h16, *q16, *k16, *v16, *hh16;
    cudaGetSymbolAddress((void**)&h16,  g_h16);
    cudaGetSymbolAddress((void**)&q16,  g_q16);
    cudaGetSymbolAddress((void**)&k16,  g_k16);
    cudaGetSymbolAddress((void**)&v16,  g_v16);
    cudaGetSymbolAddress((void**)&hh16, g_hh16);

    cudaFuncSetAttribute(attn_bf16_kernel,
                         cudaFuncAttributeMaxDynamicSharedMemorySize, ATTN_SMEM);
    const int out_smem = 4 * 8704 * 2;  // 69632 B
    cudaFuncSetAttribute(out_bf16_kernel,
                         cudaFuncAttributeMaxDynamicSharedMemorySize, out_smem);

    gncvt_kernel<<<1616, 256>>>(x, gs, gb, h16, W0, W1, W2, W3, q_cond, ka, kb);

    dim3 pg(8, 4, 48);
    proj_bf16_kernel<<<pg, 256>>>(h16, b0, b1, b2, q16, k16, v16);

    dim3 ag(8, 96);
    attn_bf16_kernel<<<ag, 256, ATTN_SMEM>>>(q16, k16, v16, hh16);

    dim3 og(8, 16);
    out_bf16_kernel<<<og, 256, out_smem>>>(hh16, b3, x, out);
}